// round 2
// baseline (speedup 1.0000x reference)
#include <cuda_runtime.h>
#include <cstdint>

// Problem constants
#define NB 64     // batch
#define NR 128    // reservoir size
#define NH 64     // image H
#define NW 64     // image W
#define ND 256    // 2*NR
#define ALPHA 0.9f

// Static device scratch (no allocations allowed).
__device__ float g_states[(size_t)NB * NH * NW * NR];  // states[b][h][w][j]
__device__ float g_A[(size_t)NB * ND * ND];            // A[b][d][e]
__device__ float g_y[NB * ND];                         // y[b][d]

// ---------------------------------------------------------------------------
// Packed f32x2 helpers (Blackwell FFMA2 path — ptxas never auto-fuses this).
// ---------------------------------------------------------------------------
typedef unsigned long long u64;

__device__ __forceinline__ u64 pack2(float lo, float hi) {
    u64 r;
    asm("mov.b64 %0, {%1, %2};" : "=l"(r) : "f"(lo), "f"(hi));
    return r;
}
__device__ __forceinline__ u64 fma2(u64 a, u64 b, u64 c) {
    u64 d;
    asm("fma.rn.f32x2 %0, %1, %2, %3;" : "=l"(d) : "l"(a), "l"(b), "l"(c));
    return d;
}
__device__ __forceinline__ float2 unpack2(u64 v) {
    float lo, hi;
    asm("mov.b64 {%0, %1}, %2;" : "=f"(lo), "=f"(hi) : "l"(v));
    return make_float2(lo, hi);
}

// ---------------------------------------------------------------------------
// Stage 1: 2D ESN recurrence. One CTA per batch element, raster order.
// 256 threads: t = j + 128*half.  half=0 -> left@W1 partial (+x*W_in, tanh,
// writeback), half=1 -> above@W2 partial.  W column pairs cached packed in
// registers; state vector read from shared as pre-packed f32x2 pairs.
// ---------------------------------------------------------------------------
__global__ void __launch_bounds__(256, 1)
rec_kernel(const float* __restrict__ x, const float* __restrict__ Win,
           const float* __restrict__ W1, const float* __restrict__ W2)
{
    int b = blockIdx.x;
    int t = threadIdx.x;
    int j = t & 127;
    int half = t >> 7;   // warp-uniform (warps 0..3 half=0, 4..7 half=1)

    __shared__ __align__(16) float row_buf[NW][NR];  // 32 KB rolling row
    __shared__ float red[NR];

    // Cache one W column as 64 packed f32x2 pairs (128 regs).
    u64 wp[64];
    const float* Wsel = half ? W2 : W1;
#pragma unroll
    for (int k = 0; k < 64; k++)
        wp[k] = pack2(Wsel[(2 * k) * 128 + j], Wsel[(2 * k + 1) * 128 + j]);
    float winj = Win[j];

    for (int i = t; i < NW * NR; i += 256) ((float*)row_buf)[i] = 0.f;
    __syncthreads();

    const float* xb = x + b * (NH * NW);
    float* sb = g_states + (size_t)b * (NH * NW * NR);

    for (int h = 0; h < NH; h++) {
        for (int w = 0; w < NW; w++) {
            // half=0 reads left = s(h,w-1) = row_buf[w-1] (zero at w==0)
            // half=1 reads above = s(h-1,w) = row_buf[w] (zero row at h==0)
            const float* src = half ? row_buf[w]
                                    : (w ? row_buf[w - 1] : (const float*)0);
            u64 acc01 = 0ull, acc23 = 0ull;   // packed (0.f,0.f)
            if (src) {
                const ulonglong2* s2 = (const ulonglong2*)src;
#pragma unroll
                for (int k4 = 0; k4 < 32; k4++) {
                    ulonglong2 v = s2[k4];    // two packed f32x2 pairs
                    acc01 = fma2(v.x, wp[2 * k4 + 0], acc01);
                    acc23 = fma2(v.y, wp[2 * k4 + 1], acc23);
                }
            }
            float2 p = unpack2(acc01), q = unpack2(acc23);
            float acc = (p.x + p.y) + (q.x + q.y);
            if (half) red[j] = acc;
            __syncthreads();
            if (!half) {
                float v = fmaf(xb[h * 64 + w], winj, acc + red[j]);
                float s = tanhf(v);
                row_buf[w][j] = s;
                sb[(h * 64 + w) * 128 + j] = s;
            }
            __syncthreads();
        }
    }
}

// ---------------------------------------------------------------------------
// Stage 2: XtX = pre^T pre (+ridge on diag), exploiting symmetry.
// pre[l=(r,c)][d] = states[b][r+1][c][d]        (d < 128, "left")
//                 = states[b][r][c+1][d-128]    (d >= 128, "above")
// Grid: (10 upper tile-pairs of 64-wide tiles, 64 batches).
// K chunked as 63 chunks of 63 samples (r = 0..62, c = 0..62).
// Inner product done as packed FFMA2.
// ---------------------------------------------------------------------------
__device__ __forceinline__ void load_tile(float X[63][64], const float* S,
                                          int r, int ti, int t)
{
    for (int idx = t; idx < 63 * 16; idx += 256) {
        int c = idx >> 4, dq = idx & 15;
        const float* p;
        if (ti < 2) p = S + ((size_t)((r + 1) * 64 + c)) * 128 + ti * 64 + dq * 4;
        else        p = S + ((size_t)(r * 64 + c + 1)) * 128 + (ti - 2) * 64 + dq * 4;
        *(float4*)&X[c][dq * 4] = *(const float4*)p;
    }
}

__global__ void __launch_bounds__(256, 2)
xtx_kernel()
{
    const int ti_map[10] = {0, 0, 0, 0, 1, 1, 1, 2, 2, 3};
    const int tj_map[10] = {0, 1, 2, 3, 1, 2, 3, 2, 3, 3};
    int ti = ti_map[blockIdx.x];
    int tj = tj_map[blockIdx.x];
    int b = blockIdx.y;
    int t = threadIdx.x;
    int tx = t & 15, ty = t >> 4;

    __shared__ __align__(16) float Xd[63][64];
    __shared__ __align__(16) float Xe[63][64];

    u64 accp[4][2];   // accp[i][0] = (acc[i][0],acc[i][1]), [1] = ([2],[3])
#pragma unroll
    for (int i = 0; i < 4; i++) { accp[i][0] = 0ull; accp[i][1] = 0ull; }

    const float* S = g_states + (size_t)b * (NH * NW * NR);

    for (int r = 0; r < 63; r++) {
        load_tile(Xd, S, r, ti, t);
        load_tile(Xe, S, r, tj, t);
        __syncthreads();
#pragma unroll 9
        for (int c = 0; c < 63; c++) {
            float4 av = *(const float4*)&Xd[c][tx * 4];
            ulonglong2 ev = *(const ulonglong2*)&Xe[c][ty * 4]; // pre-packed pairs
            u64 a0 = pack2(av.x, av.x);
            u64 a1 = pack2(av.y, av.y);
            u64 a2 = pack2(av.z, av.z);
            u64 a3 = pack2(av.w, av.w);
            accp[0][0] = fma2(a0, ev.x, accp[0][0]);
            accp[0][1] = fma2(a0, ev.y, accp[0][1]);
            accp[1][0] = fma2(a1, ev.x, accp[1][0]);
            accp[1][1] = fma2(a1, ev.y, accp[1][1]);
            accp[2][0] = fma2(a2, ev.x, accp[2][0]);
            accp[2][1] = fma2(a2, ev.y, accp[2][1]);
            accp[3][0] = fma2(a3, ev.x, accp[3][0]);
            accp[3][1] = fma2(a3, ev.y, accp[3][1]);
        }
        __syncthreads();
    }

    float* Ab = g_A + (size_t)b * (ND * ND);
    int e0 = tj * 64 + ty * 4;
#pragma unroll
    for (int ii = 0; ii < 4; ii++) {
        int d = ti * 64 + tx * 4 + ii;
        float2 e01 = unpack2(accp[ii][0]);
        float2 e23 = unpack2(accp[ii][1]);
        float4 vv = make_float4(e01.x, e01.y, e23.x, e23.y);
        if (ti == tj) {
            if (d >= e0 && d < e0 + 4) (&vv.x)[d - e0] += ALPHA;  // ridge
            *(float4*)&Ab[d * ND + e0] = vv;
        } else {
            *(float4*)&Ab[d * ND + e0] = vv;
            Ab[(e0 + 0) * ND + d] = vv.x;
            Ab[(e0 + 1) * ND + d] = vv.y;
            Ab[(e0 + 2) * ND + d] = vv.z;
            Ab[(e0 + 3) * ND + d] = vv.w;
        }
    }
}

// ---------------------------------------------------------------------------
// Stage 3: Xty[b][d] = sum_l pre[l][d] * x[b][1+r][1+c]
// ---------------------------------------------------------------------------
__global__ void __launch_bounds__(256, 4)
xty_kernel(const float* __restrict__ x)
{
    int b = blockIdx.x;
    int d = threadIdx.x;  // 0..255; warp-uniform d<128 split
    const float* S = g_states + (size_t)b * (NH * NW * NR);
    const float* xb = x + b * (NH * NW);
    float acc = 0.f;
    for (int r = 0; r < 63; r++) {
#pragma unroll 7
        for (int c = 0; c < 63; c++) {
            float xv = xb[(r + 1) * 64 + (c + 1)];
            float sv;
            if (d < 128) sv = S[((size_t)((r + 1) * 64 + c)) * 128 + d];
            else         sv = S[((size_t)(r * 64 + c + 1)) * 128 + (d - 128)];
            acc = fmaf(sv, xv, acc);
        }
    }
    g_y[b * ND + d] = acc;
}

// ---------------------------------------------------------------------------
// Stage 4: per-batch Gauss-Jordan on A (SPD + ridge, no pivoting needed).
// Only columns j >= k are live after step k. One CTA per batch.
// ---------------------------------------------------------------------------
__global__ void __launch_bounds__(256, 1)
solve_kernel(float* __restrict__ out)
{
    int b = blockIdx.x;
    int t = threadIdx.x;
    float* Ab = g_A + (size_t)b * (ND * ND);
    float* yb = g_y + b * ND;
    __shared__ float prow[ND];
    __shared__ float fcol[ND];

    int jq = t & 63;   // owns columns 4*jq .. 4*jq+3
    int ig = t >> 6;   // rows ig*64 .. ig*64+63

    for (int k = 0; k < ND; k++) {
        prow[t] = Ab[k * ND + t];
        __syncthreads();
        float inv = 1.0f / prow[k];
        fcol[t] = (t == k) ? 0.0f : Ab[t * ND + k] * inv;
        __syncthreads();
        if (jq * 4 + 3 >= k) {
            float4 pv = *(const float4*)&prow[jq * 4];
            int i0 = ig * 64;
#pragma unroll 8
            for (int i = i0; i < i0 + 64; i++) {
                float f = fcol[i];
                float4 a = *(float4*)&Ab[i * ND + jq * 4];
                a.x = fmaf(-f, pv.x, a.x);
                a.y = fmaf(-f, pv.y, a.y);
                a.z = fmaf(-f, pv.z, a.z);
                a.w = fmaf(-f, pv.w, a.w);
                *(float4*)&Ab[i * ND + jq * 4] = a;
            }
        }
        float yk = yb[k];
        if (t != k) yb[t] -= fcol[t] * yk;
        __syncthreads();
    }
    out[b * ND + t] = yb[t] / Ab[t * ND + t];
}

// ---------------------------------------------------------------------------
extern "C" void kernel_launch(void* const* d_in, const int* in_sizes, int n_in,
                              void* d_out, int out_size)
{
    const float* x   = (const float*)d_in[0];  // (64,64,64)
    const float* Win = (const float*)d_in[1];  // (1,128)
    const float* W1  = (const float*)d_in[2];  // (128,128)
    const float* W2  = (const float*)d_in[3];  // (128,128)
    float* out = (float*)d_out;                // (64,256)

    rec_kernel<<<NB, 256>>>(x, Win, W1, W2);
    xtx_kernel<<<dim3(10, NB), 256>>>();
    xty_kernel<<<NB, 256>>>(x);
    solve_kernel<<<NB, 256>>>(out);
}

// round 13
// speedup vs baseline: 1.2603x; 1.2603x over previous
#include <cuda_runtime.h>
#include <cstdint>

// Problem constants
#define NB 64     // batch
#define NR 128    // reservoir size
#define NH 64     // image H
#define NW 64     // image W
#define ND 256    // 2*NR
#define ALPHA 0.9f

// Static device scratch (no allocations allowed).
__device__ float g_states[(size_t)NB * NH * NW * NR];  // states[b][h][w][j]
__device__ float g_A[(size_t)NB * ND * ND];            // A[b][d][e]
__device__ float g_y[NB * ND];                         // y[b][d]

// ---------------------------------------------------------------------------
// Packed f32x2 helpers (Blackwell FFMA2 path — ptxas never auto-fuses this).
// ---------------------------------------------------------------------------
typedef unsigned long long u64;

__device__ __forceinline__ u64 pack2(float lo, float hi) {
    u64 r;
    asm("mov.b64 %0, {%1, %2};" : "=l"(r) : "f"(lo), "f"(hi));
    return r;
}
__device__ __forceinline__ u64 fma2(u64 a, u64 b, u64 c) {
    u64 d;
    asm("fma.rn.f32x2 %0, %1, %2, %3;" : "=l"(d) : "l"(a), "l"(b), "l"(c));
    return d;
}
__device__ __forceinline__ float2 unpack2(u64 v) {
    float lo, hi;
    asm("mov.b64 {%0, %1}, %2;" : "=f"(lo), "=f"(hi) : "l"(v));
    return make_float2(lo, hi);
}

// 128-long dot of a broadcast smem vector with a register-cached packed column.
// 4 accumulator chains -> dependency depth 16*4 = 64 cyc.
__device__ __forceinline__ float dot128(const float* s, const u64* wp) {
    const ulonglong2* s2 = (const ulonglong2*)s;
    u64 a0 = 0ull, a1 = 0ull, a2 = 0ull, a3 = 0ull;
#pragma unroll
    for (int k = 0; k < 16; k++) {
        ulonglong2 v0 = s2[2 * k];
        ulonglong2 v1 = s2[2 * k + 1];
        a0 = fma2(v0.x, wp[4 * k + 0], a0);
        a1 = fma2(v0.y, wp[4 * k + 1], a1);
        a2 = fma2(v1.x, wp[4 * k + 2], a2);
        a3 = fma2(v1.y, wp[4 * k + 3], a3);
    }
    float2 p = unpack2(a0), q = unpack2(a1), r = unpack2(a2), u = unpack2(a3);
    return ((p.x + p.y) + (q.x + q.y)) + ((r.x + r.y) + (u.x + u.y));
}

// ---------------------------------------------------------------------------
// Stage 1: 2D ESN recurrence, software-pipelined, with Xty FUSED.
// One CTA per batch element. half0 (t<128): left-dot (W1) + tanh + writeback
// + y accumulation for cell (h,w). half1: above-dot (W2) for cell (h,w+1),
// one step AHEAD into apipe. ONE __syncthreads per cell.
//
// Xty fusion: s(h,w)[j] contributes
//   to y[j]      (left slot)  with weight x[h][w+1]  iff h>=1 && w<=62
//   to y[128+j]  (above slot) with weight x[h+1][w]  iff h<=62 && w>=1
// ---------------------------------------------------------------------------
__global__ void __launch_bounds__(256, 1)
rec_kernel(const float* __restrict__ x, const float* __restrict__ Win,
           const float* __restrict__ W1, const float* __restrict__ W2)
{
    int b = blockIdx.x;
    int t = threadIdx.x;
    int j = t & 127;
    int half = t >> 7;   // warp-uniform

    __shared__ __align__(16) float row_buf[NW][NR];  // rolling row of states
    __shared__ __align__(16) float apipe[2][NR];     // above-contrib pipeline
    __shared__ float xrow[NW];                       // x row h
    __shared__ float xnext[NW];                      // x row h+1

    // Cache one W column as 64 packed f32x2 pairs (128 regs).
    u64 wp[64];
    const float* Wsel = half ? W2 : W1;
#pragma unroll
    for (int k = 0; k < 64; k++)
        wp[k] = pack2(Wsel[(2 * k) * 128 + j], Wsel[(2 * k + 1) * 128 + j]);
    float winj = Win[j];

    for (int i = t; i < NW * NR; i += 256) ((float*)row_buf)[i] = 0.f;
    __syncthreads();

    const float* xb = x + b * (NH * NW);
    float* sb = g_states + (size_t)b * (NH * NW * NR);

    float yl = 0.f, ya = 0.f;   // fused Xty accumulators (half0 only)

    for (int h = 0; h < NH; h++) {
        // Prologue: half1 fills apipe[0] for cell (h,0) from row_buf[0]
        // (= s(h-1,0); zeros for h==0). half0 stages x rows h and h+1.
        if (half) {
            apipe[0][j] = dot128(row_buf[0], wp);
        } else if (t < NW) {
            xrow[t] = xb[h * NW + t];
        } else {
            int c = t - NW;  // 0..63
            xnext[c] = (h + 1 < NH) ? xb[(h + 1) * NW + c] : 0.f;
        }
        __syncthreads();

        for (int w = 0; w < NW; w++) {
            if (!half) {
                float left = (w > 0) ? dot128(row_buf[w - 1], wp) : 0.f;
                float v = fmaf(xrow[w], winj, left + apipe[w & 1][j]);
                float s = tanhf(v);
                row_buf[w][j] = s;
                sb[(h * NW + w) * NR + j] = s;
                // fused Xty accumulation
                if (h >= 1 && w <= NW - 2) yl = fmaf(s, xrow[w + 1], yl);
                if (h <= NH - 2 && w >= 1) ya = fmaf(s, xnext[w], ya);
            } else if (w < NW - 1) {
                // above for cell (h,w+1): row_buf[w+1] still holds s(h-1,w+1)
                apipe[(w + 1) & 1][j] = dot128(row_buf[w + 1], wp);
            }
            __syncthreads();
        }
    }

    if (!half) {
        g_y[b * ND + j] = yl;
        g_y[b * ND + 128 + j] = ya;
    }
}

// ---------------------------------------------------------------------------
// Stage 2: XtX = pre^T pre (+ridge on diag), exploiting symmetry.
// pre[l=(r,c)][d] = states[b][r+1][c][d]        (d < 128, "left")
//                 = states[b][r][c+1][d-128]    (d >= 128, "above")
// Grid: (10 upper tile-pairs of 64-wide tiles, 64 batches).
// K chunked as 63 chunks of 63 samples (r = 0..62, c = 0..62).
// ---------------------------------------------------------------------------
__device__ __forceinline__ void load_tile(float X[63][64], const float* S,
                                          int r, int ti, int t)
{
    for (int idx = t; idx < 63 * 16; idx += 256) {
        int c = idx >> 4, dq = idx & 15;
        const float* p;
        if (ti < 2) p = S + ((size_t)((r + 1) * 64 + c)) * 128 + ti * 64 + dq * 4;
        else        p = S + ((size_t)(r * 64 + c + 1)) * 128 + (ti - 2) * 64 + dq * 4;
        *(float4*)&X[c][dq * 4] = *(const float4*)p;
    }
}

__global__ void __launch_bounds__(256, 2)
xtx_kernel()
{
    const int ti_map[10] = {0, 0, 0, 0, 1, 1, 1, 2, 2, 3};
    const int tj_map[10] = {0, 1, 2, 3, 1, 2, 3, 2, 3, 3};
    int ti = ti_map[blockIdx.x];
    int tj = tj_map[blockIdx.x];
    int b = blockIdx.y;
    int t = threadIdx.x;
    int tx = t & 15, ty = t >> 4;

    __shared__ __align__(16) float Xd[63][64];
    __shared__ __align__(16) float Xe[63][64];

    u64 accp[4][2];
#pragma unroll
    for (int i = 0; i < 4; i++) { accp[i][0] = 0ull; accp[i][1] = 0ull; }

    const float* S = g_states + (size_t)b * (NH * NW * NR);

    for (int r = 0; r < 63; r++) {
        load_tile(Xd, S, r, ti, t);
        load_tile(Xe, S, r, tj, t);
        __syncthreads();
#pragma unroll 9
        for (int c = 0; c < 63; c++) {
            float4 av = *(const float4*)&Xd[c][tx * 4];
            ulonglong2 ev = *(const ulonglong2*)&Xe[c][ty * 4];
            u64 a0 = pack2(av.x, av.x);
            u64 a1 = pack2(av.y, av.y);
            u64 a2 = pack2(av.z, av.z);
            u64 a3 = pack2(av.w, av.w);
            accp[0][0] = fma2(a0, ev.x, accp[0][0]);
            accp[0][1] = fma2(a0, ev.y, accp[0][1]);
            accp[1][0] = fma2(a1, ev.x, accp[1][0]);
            accp[1][1] = fma2(a1, ev.y, accp[1][1]);
            accp[2][0] = fma2(a2, ev.x, accp[2][0]);
            accp[2][1] = fma2(a2, ev.y, accp[2][1]);
            accp[3][0] = fma2(a3, ev.x, accp[3][0]);
            accp[3][1] = fma2(a3, ev.y, accp[3][1]);
        }
        __syncthreads();
    }

    float* Ab = g_A + (size_t)b * (ND * ND);
    int e0 = tj * 64 + ty * 4;
#pragma unroll
    for (int ii = 0; ii < 4; ii++) {
        int d = ti * 64 + tx * 4 + ii;
        float2 e01 = unpack2(accp[ii][0]);
        float2 e23 = unpack2(accp[ii][1]);
        float4 vv = make_float4(e01.x, e01.y, e23.x, e23.y);
        if (ti == tj) {
            if (d >= e0 && d < e0 + 4) (&vv.x)[d - e0] += ALPHA;  // ridge
            *(float4*)&Ab[d * ND + e0] = vv;
        } else {
            *(float4*)&Ab[d * ND + e0] = vv;
            Ab[(e0 + 0) * ND + d] = vv.x;
            Ab[(e0 + 1) * ND + d] = vv.y;
            Ab[(e0 + 2) * ND + d] = vv.z;
            Ab[(e0 + 3) * ND + d] = vv.w;
        }
    }
}

// ---------------------------------------------------------------------------
// Stage 4: blocked right-looking LU (no pivoting; A is SPD + ridge), panel
// width 64, panel rows held in REGISTERS (thread t owns global row k0+t).
// Pivot rows published to smem -> no n^3 L2 traffic. y forward-eliminated
// in-flight; blocked back-substitution at the end. One CTA per batch.
// ---------------------------------------------------------------------------
#define SN 256
#define SBK 64
#define SPAD 68   // row stride (floats): multiple of 4 for float4/16B alignment

__global__ void __launch_bounds__(256, 1)
solve_kernel(float* __restrict__ out)
{
    int b = blockIdx.x;
    int t = threadIdx.x;
    float* Ab = g_A + (size_t)b * SN * SN;

    __shared__ float L11[SBK][SPAD];  // published (final) panel rows
    __shared__ float Us[SBK][SPAD];   // current right block (U12 candidate)
    __shared__ float ys[SN];
    __shared__ float xs[SN];

    ys[t] = g_y[b * SN + t];
    __syncthreads();

    float row[SBK];  // thread-owned panel row (cols k0..k0+63 of row k0+t)

    for (int p = 0; p < 4; p++) {
        int k0 = p * SBK;
        int R = SN - k0;
        bool mine = (t < R);

        if (mine) {
            const float4* src = (const float4*)&Ab[(size_t)(k0 + t) * SN + k0];
#pragma unroll
            for (int q = 0; q < 16; q++) {
                float4 v = src[q];
                row[4 * q] = v.x; row[4 * q + 1] = v.y;
                row[4 * q + 2] = v.z; row[4 * q + 3] = v.w;
            }
        }

        // ---- panel factorization (rows in regs, pivots via smem) ----
        for (int kk = 0; kk < SBK; kk++) {
            if (t == kk) {
#pragma unroll
                for (int q = 0; q < 16; q++)
                    *(float4*)&L11[kk][4 * q] =
                        make_float4(row[4 * q], row[4 * q + 1],
                                    row[4 * q + 2], row[4 * q + 3]);
            }
            __syncthreads();
            if (mine && t > kk) {
                float m = row[kk] * (1.0f / L11[kk][kk]);
                row[kk] = m;
#pragma unroll 4
                for (int jj = kk + 1; jj < SBK; jj++)
                    row[jj] = fmaf(-m, L11[kk][jj], row[jj]);
                ys[k0 + t] = fmaf(-m, ys[k0 + kk], ys[k0 + t]);
            }
            __syncthreads();  // ys pivot for next step must be visible
        }

        // write back factor block (rows k0..k0+63, cols k0..k0+63)
        for (int idx = t; idx < SBK * SBK; idx += 256) {
            int i = idx >> 6, jj = idx & 63;
            Ab[(size_t)(k0 + i) * SN + k0 + jj] = L11[i][jj];
        }

        // ---- right blocks: tri-solve U12 = L11^{-1} A12, then trailing ----
        for (int qb = p + 1; qb < 4; qb++) {
            int c0 = qb * SBK;
            __syncthreads();  // Us reuse barrier
            for (int idx = t; idx < SBK * SBK; idx += 256) {
                int i = idx >> 6, jj = idx & 63;
                Us[i][jj] = Ab[(size_t)(k0 + i) * SN + c0 + jj];
            }
            __syncthreads();

            // unit-lower tri-solve in smem
            {
                int ii0 = t >> 6;   // 0..3
                int jj = t & 63;
                for (int m = 0; m < SBK - 1; m++) {
                    float um = Us[m][jj];
                    int start = (m + 1) + (((ii0 - (m + 1)) & 3));
                    for (int i = start; i < SBK; i += 4)
                        Us[i][jj] = fmaf(-L11[i][m], um, Us[i][jj]);
                    __syncthreads();
                }
            }

            // write back U12
            for (int idx = t; idx < SBK * SBK; idx += 256) {
                int i = idx >> 6, jj = idx & 63;
                Ab[(size_t)(k0 + i) * SN + c0 + jj] = Us[i][jj];
            }

            // trailing update: rows k0+64..255 (thread t >= 64 owns row k0+t)
            if (t >= SBK && mine) {
                float* crow = &Ab[(size_t)(k0 + t) * SN + c0];
                u64 acc[32];
#pragma unroll
                for (int q = 0; q < 16; q++) {
                    float4 v = *(float4*)&crow[4 * q];
                    acc[2 * q] = pack2(v.x, v.y);
                    acc[2 * q + 1] = pack2(v.z, v.w);
                }
#pragma unroll 4
                for (int m = 0; m < SBK; m++) {
                    u64 lm = pack2(-row[m], -row[m]);
                    const ulonglong2* ur = (const ulonglong2*)&Us[m][0];
#pragma unroll
                    for (int q = 0; q < 16; q++) {
                        ulonglong2 uv = ur[q];
                        acc[2 * q] = fma2(lm, uv.x, acc[2 * q]);
                        acc[2 * q + 1] = fma2(lm, uv.y, acc[2 * q + 1]);
                    }
                }
#pragma unroll
                for (int q = 0; q < 16; q++) {
                    float2 e0 = unpack2(acc[2 * q]);
                    float2 e1 = unpack2(acc[2 * q + 1]);
                    *(float4*)&crow[4 * q] = make_float4(e0.x, e0.y, e1.x, e1.y);
                }
            }
        }
        __syncthreads();
    }

    // ---- blocked back-substitution: solve U xs = ys ----
    for (int p = 3; p >= 0; p--) {
        int k0 = p * SBK;
        for (int idx = t; idx < SBK * SBK; idx += 256) {
            int i = idx >> 6, jj = idx & 63;
            L11[i][jj] = Ab[(size_t)(k0 + i) * SN + k0 + jj];
        }
        __syncthreads();
        for (int jj = SBK - 1; jj >= 0; jj--) {
            if (t == 0) xs[k0 + jj] = ys[k0 + jj] / L11[jj][jj];
            __syncthreads();
            if (t < jj) ys[k0 + t] = fmaf(-L11[t][jj], xs[k0 + jj], ys[k0 + t]);
            __syncthreads();
        }
        // ys[0..k0-1] -= A[r][k0..k0+63] @ xs[k0..k0+63]
        if (t < k0) {
            const float4* ur = (const float4*)&Ab[(size_t)t * SN + k0];
            u64 a01 = 0ull, a23 = 0ull;
#pragma unroll
            for (int q = 0; q < 16; q++) {
                float4 uv = ur[q];
                float4 xv = *(float4*)&xs[k0 + 4 * q];
                a01 = fma2(pack2(uv.x, uv.y), pack2(-xv.x, -xv.y), a01);
                a23 = fma2(pack2(uv.z, uv.w), pack2(-xv.z, -xv.w), a23);
            }
            float2 e0 = unpack2(a01), e1 = unpack2(a23);
            ys[t] += (e0.x + e0.y) + (e1.x + e1.y);
        }
        __syncthreads();
    }

    out[b * SN + t] = xs[t];
}

// ---------------------------------------------------------------------------
extern "C" void kernel_launch(void* const* d_in, const int* in_sizes, int n_in,
                              void* d_out, int out_size)
{
    const float* x   = (const float*)d_in[0];  // (64,64,64)
    const float* Win = (const float*)d_in[1];  // (1,128)
    const float* W1  = (const float*)d_in[2];  // (128,128)
    const float* W2  = (const float*)d_in[3];  // (128,128)
    float* out = (float*)d_out;                // (64,256)

    rec_kernel<<<NB, 256>>>(x, Win, W1, W2);   // states + fused Xty
    xtx_kernel<<<dim3(10, NB), 256>>>();
    solve_kernel<<<NB, 256>>>(out);
}